// round 1
// baseline (speedup 1.0000x reference)
#include <cuda_runtime.h>
#include <math.h>

// Problem dims (fixed by the reference)
#define B_  512
#define XD  768
#define YD  128
#define H2_ 512

// Scratch (no allocations allowed -> __device__ globals)
__device__ float  g_Hmu[B_ * H2_];
__device__ float  g_Hlv[B_ * H2_];
__device__ float  g_mu [B_ * YD];
__device__ float  g_lv [B_ * YD];
__device__ float  g_iv [B_ * YD];
__device__ double g_Sy [YD];
__device__ double g_Sy2[YD];
__device__ double g_pos_row[B_];
__device__ double g_all_row[B_];

// ---------------------------------------------------------------------------
// GEMM1: H = relu(X @ W1 + b1), X:(512,768), W1:(768,512).
// blockIdx.z selects mu(0) / lv(1) path. BM=BN=64, BK=16, 256 thr, 4x4 micro.
// ---------------------------------------------------------------------------
__global__ __launch_bounds__(256) void k_gemm1(
    const float* __restrict__ X,
    const float* __restrict__ Wmu, const float* __restrict__ bmu,
    const float* __restrict__ Wlv, const float* __restrict__ blv)
{
    const bool  lvp  = (blockIdx.z != 0);
    const float* W   = lvp ? Wlv : Wmu;
    const float* bia = lvp ? blv : bmu;
    float*       H   = lvp ? g_Hlv : g_Hmu;

    __shared__ float As[16][68];   // [k][m], padded
    __shared__ float Bs[16][64];   // [k][n]

    const int tid = threadIdx.x;
    const int tx  = tid & 15;      // col group
    const int ty  = tid >> 4;      // row group
    const int m0  = blockIdx.y * 64;
    const int n0  = blockIdx.x * 64;

    const int arow = tid >> 2;           // 0..63
    const int ak   = (tid & 3) << 2;     // 0,4,8,12
    const int brow = tid >> 4;           // 0..15
    const int bcol = (tid & 15) << 2;    // 0..60

    float acc[4][4] = {};

    for (int k0 = 0; k0 < XD; k0 += 16) {
        float4 a4 = *(const float4*)(X + (m0 + arow) * XD + k0 + ak);
        float4 b4 = *(const float4*)(W + (k0 + brow) * H2_ + n0 + bcol);
        As[ak + 0][arow] = a4.x;
        As[ak + 1][arow] = a4.y;
        As[ak + 2][arow] = a4.z;
        As[ak + 3][arow] = a4.w;
        *(float4*)(&Bs[brow][bcol]) = b4;
        __syncthreads();

        #pragma unroll
        for (int kk = 0; kk < 16; kk++) {
            float4 av = *(const float4*)(&As[kk][ty * 4]);
            float4 bv = *(const float4*)(&Bs[kk][tx * 4]);
            float a[4] = {av.x, av.y, av.z, av.w};
            float b[4] = {bv.x, bv.y, bv.z, bv.w};
            #pragma unroll
            for (int i = 0; i < 4; i++)
                #pragma unroll
                for (int j = 0; j < 4; j++)
                    acc[i][j] = fmaf(a[i], b[j], acc[i][j]);
        }
        __syncthreads();
    }

    const int col = n0 + tx * 4;
    float4 bb = *(const float4*)(bia + col);
    #pragma unroll
    for (int i = 0; i < 4; i++) {
        int row = m0 + ty * 4 + i;
        float4 o;
        o.x = fmaxf(acc[i][0] + bb.x, 0.0f);
        o.y = fmaxf(acc[i][1] + bb.y, 0.0f);
        o.z = fmaxf(acc[i][2] + bb.z, 0.0f);
        o.w = fmaxf(acc[i][3] + bb.w, 0.0f);
        *(float4*)(H + row * H2_ + col) = o;
    }
}

// ---------------------------------------------------------------------------
// GEMM2: out = H @ W2 + b2. mu path: store mu. lv path: lv=tanh(.), iv=exp(-lv).
// BM=32, BN=64, BK=16, 256 thr, 2x4 micro. grid = (2, 16, 2)
// ---------------------------------------------------------------------------
__global__ __launch_bounds__(256) void k_gemm2(
    const float* __restrict__ W2mu, const float* __restrict__ b2mu,
    const float* __restrict__ W2lv, const float* __restrict__ b2lv)
{
    const bool  lvp  = (blockIdx.z != 0);
    const float* H   = lvp ? g_Hlv : g_Hmu;
    const float* W   = lvp ? W2lv : W2mu;
    const float* bia = lvp ? b2lv : b2mu;

    __shared__ float As[16][36];   // [k][m], padded
    __shared__ float Bs[16][64];   // [k][n]

    const int tid = threadIdx.x;
    const int tx  = tid & 15;
    const int ty  = tid >> 4;
    const int m0  = blockIdx.y * 32;
    const int n0  = blockIdx.x * 64;

    const int arow = tid >> 3;          // 0..31
    const int ak   = (tid & 7) << 1;    // 0..14
    const int brow = tid >> 4;          // 0..15
    const int bcol = (tid & 15) << 2;   // 0..60

    float acc[2][4] = {};

    for (int k0 = 0; k0 < H2_; k0 += 16) {
        float2 a2 = *(const float2*)(H + (m0 + arow) * H2_ + k0 + ak);
        float4 b4 = *(const float4*)(W + (k0 + brow) * YD + n0 + bcol);
        As[ak + 0][arow] = a2.x;
        As[ak + 1][arow] = a2.y;
        *(float4*)(&Bs[brow][bcol]) = b4;
        __syncthreads();

        #pragma unroll
        for (int kk = 0; kk < 16; kk++) {
            float2 av = *(const float2*)(&As[kk][ty * 2]);
            float4 bv = *(const float4*)(&Bs[kk][tx * 4]);
            float a[2] = {av.x, av.y};
            float b[4] = {bv.x, bv.y, bv.z, bv.w};
            #pragma unroll
            for (int i = 0; i < 2; i++)
                #pragma unroll
                for (int j = 0; j < 4; j++)
                    acc[i][j] = fmaf(a[i], b[j], acc[i][j]);
        }
        __syncthreads();
    }

    const int col = n0 + tx * 4;
    float4 bb = *(const float4*)(bia + col);
    #pragma unroll
    for (int i = 0; i < 2; i++) {
        int row = m0 + ty * 2 + i;
        float s0 = acc[i][0] + bb.x;
        float s1 = acc[i][1] + bb.y;
        float s2 = acc[i][2] + bb.z;
        float s3 = acc[i][3] + bb.w;
        if (!lvp) {
            float4 o = {s0, s1, s2, s3};
            *(float4*)(g_mu + row * YD + col) = o;
        } else {
            float t0 = tanhf(s0), t1 = tanhf(s1), t2 = tanhf(s2), t3 = tanhf(s3);
            float4 ol = {t0, t1, t2, t3};
            float4 oi = {expf(-t0), expf(-t1), expf(-t2), expf(-t3)};
            *(float4*)(g_lv + row * YD + col) = ol;
            *(float4*)(g_iv + row * YD + col) = oi;
        }
    }
}

// ---------------------------------------------------------------------------
// y column stats: Sy[d] = sum_j y[j,d], Sy2[d] = sum_j y[j,d]^2 (fp64 accum)
// ---------------------------------------------------------------------------
__global__ __launch_bounds__(YD) void k_ystats(const float* __restrict__ Y)
{
    const int d = threadIdx.x;
    double sy = 0.0, sy2 = 0.0;
    for (int j = 0; j < B_; j++) {
        double v = (double)Y[j * YD + d];
        sy  += v;
        sy2 += v * v;
    }
    g_Sy[d]  = sy;
    g_Sy2[d] = sy2;
}

// ---------------------------------------------------------------------------
// Per-row reductions (fp64):
//  pos_i   = sum_d [-0.5 (mu-y)^2 iv - 0.5 lv]
//  rowall_i= sum_j all_probs[i,j]
//          = sum_d [-0.5 iv (Sy2 - 2 mu Sy + 512 mu^2) - 256 lv]
// ---------------------------------------------------------------------------
__global__ __launch_bounds__(YD) void k_rows(const float* __restrict__ Y)
{
    const int i = blockIdx.x;
    const int d = threadIdx.x;

    double mu = (double)g_mu[i * YD + d];
    double lv = (double)g_lv[i * YD + d];
    double iv = (double)g_iv[i * YD + d];
    double y  = (double)Y   [i * YD + d];

    double dmy = mu - y;
    double pos = -0.5 * dmy * dmy * iv - 0.5 * lv;
    double row = -0.5 * iv * (g_Sy2[d] - 2.0 * mu * g_Sy[d] + 512.0 * mu * mu)
                 - 256.0 * lv;

    __shared__ double sp[YD];
    __shared__ double sa[YD];
    sp[d] = pos;
    sa[d] = row;
    __syncthreads();
    #pragma unroll
    for (int s = YD / 2; s > 0; s >>= 1) {
        if (d < s) { sp[d] += sp[d + s]; sa[d] += sa[d + s]; }
        __syncthreads();
    }
    if (d == 0) {
        g_pos_row[i] = sp[0];
        g_all_row[i] = sa[0];
    }
}

// ---------------------------------------------------------------------------
// Final deterministic tree reduce: out = mean(pos) - mean(all_probs)
// (negative == all_probs exactly in fp32: logsumexp constant cancels log(B-1))
// ---------------------------------------------------------------------------
__global__ __launch_bounds__(B_) void k_final(float* __restrict__ out, int out_size)
{
    const int t = threadIdx.x;
    __shared__ double sp[B_];
    __shared__ double sa[B_];
    sp[t] = g_pos_row[t];
    sa[t] = g_all_row[t];
    __syncthreads();
    #pragma unroll
    for (int s = B_ / 2; s > 0; s >>= 1) {
        if (t < s) { sp[t] += sp[t + s]; sa[t] += sa[t + s]; }
        __syncthreads();
    }
    if (t == 0) {
        double res = sp[0] / 512.0 - sa[0] / (512.0 * 512.0);
        out[0] = (float)res;
    }
    // defensive: zero any extra output elements (poisoned by harness)
    for (int k = t + 1; k < out_size; k += B_) out[k] = 0.0f;
}

// ---------------------------------------------------------------------------
extern "C" void kernel_launch(void* const* d_in, const int* in_sizes, int n_in,
                              void* d_out, int out_size)
{
    const float* x   = (const float*)d_in[0];
    const float* y   = (const float*)d_in[1];
    const float* w1m = (const float*)d_in[2];
    const float* b1m = (const float*)d_in[3];
    const float* w2m = (const float*)d_in[4];
    const float* b2m = (const float*)d_in[5];
    const float* w1l = (const float*)d_in[6];
    const float* b1l = (const float*)d_in[7];
    const float* w2l = (const float*)d_in[8];
    const float* b2l = (const float*)d_in[9];

    dim3 g1(H2_ / 64, B_ / 64, 2);   // (8, 8, 2) = 128 blocks
    k_gemm1<<<g1, 256>>>(x, w1m, b1m, w1l, b1l);

    dim3 g2(YD / 64, B_ / 32, 2);    // (2, 16, 2) = 64 blocks
    k_gemm2<<<g2, 256>>>(w2m, b2m, w2l, b2l);

    k_ystats<<<1, YD>>>(y);
    k_rows<<<B_, YD>>>(y);
    k_final<<<1, B_>>>((float*)d_out, out_size);
}

// round 2
// speedup vs baseline: 1.3742x; 1.3742x over previous
#include <cuda_runtime.h>
#include <math.h>

// Problem dims (fixed by the reference)
#define B_  512
#define XD  768
#define YD  128
#define H2_ 512
#define NPART 16

typedef unsigned long long u64;

// Scratch (no allocations allowed -> __device__ globals)
__device__ float  g_Hmu[B_ * H2_];
__device__ float  g_Hlv[B_ * H2_];
__device__ float  g_mu [B_ * YD];
__device__ float  g_lv [B_ * YD];
__device__ float  g_iv [B_ * YD];
__device__ double g_SyP [NPART][YD];
__device__ double g_Sy2P[NPART][YD];
__device__ double g_pos_row[B_];
__device__ double g_all_row[B_];

// ---------------- f32x2 packed-FMA helpers (Blackwell FFMA2) ----------------
__device__ __forceinline__ u64 pack2(float lo, float hi) {
    u64 r; asm("mov.b64 %0, {%1, %2};" : "=l"(r) : "f"(lo), "f"(hi)); return r;
}
__device__ __forceinline__ void fma2(u64 &d, u64 a, u64 b) {
    asm("fma.rn.f32x2 %0, %1, %2, %0;" : "+l"(d) : "l"(a), "l"(b));
}
__device__ __forceinline__ float2 unpack2(u64 v) {
    float2 f; asm("mov.b64 {%0, %1}, %2;" : "=f"(f.x), "=f"(f.y) : "l"(v)); return f;
}

// ---------------------------------------------------------------------------
// GEMM1: H = relu(X @ W1 + b1), X:(512,768), W1:(768,512).
// BM=BN=64, BK=16, 256 thr, 4x4 micro via FFMA2. grid (8,8,2) = 128 blocks.
// A fragment stored duplicated ({a,a} u64) in smem so inner loop has no MOVs.
// ---------------------------------------------------------------------------
__global__ __launch_bounds__(256) void k_gemm1(
    const float* __restrict__ X,
    const float* __restrict__ Wmu, const float* __restrict__ bmu,
    const float* __restrict__ Wlv, const float* __restrict__ blv)
{
    const bool  lvp  = (blockIdx.z != 0);
    const float* W   = lvp ? Wlv : Wmu;
    const float* bia = lvp ? blv : bmu;
    float*       H   = lvp ? g_Hlv : g_Hmu;

    __shared__ u64   As2[16][64];   // [k][m], each entry duplicated {a,a}
    __shared__ float Bs [16][64];   // [k][n]

    const int tid = threadIdx.x;
    const int tx  = tid & 15;      // n group (4 cols)
    const int ty  = tid >> 4;      // m group (4 rows)
    const int m0  = blockIdx.y * 64;
    const int n0  = blockIdx.x * 64;

    const int arow = tid >> 2;           // 0..63
    const int ak   = (tid & 3) << 2;     // 0,4,8,12
    const int brow = tid >> 4;           // 0..15
    const int bcol = (tid & 15) << 2;    // 0..60

    u64 acc[4][2] = {};

    for (int k0 = 0; k0 < XD; k0 += 16) {
        float4 a4 = *(const float4*)(X + (m0 + arow) * XD + k0 + ak);
        float4 b4 = *(const float4*)(W + (k0 + brow) * H2_ + n0 + bcol);
        As2[ak + 0][arow] = pack2(a4.x, a4.x);
        As2[ak + 1][arow] = pack2(a4.y, a4.y);
        As2[ak + 2][arow] = pack2(a4.z, a4.z);
        As2[ak + 3][arow] = pack2(a4.w, a4.w);
        *(float4*)(&Bs[brow][bcol]) = b4;
        __syncthreads();

        #pragma unroll
        for (int kk = 0; kk < 16; kk++) {
            ulonglong2 a01 = *(const ulonglong2*)(&As2[kk][ty * 4 + 0]);
            ulonglong2 a23 = *(const ulonglong2*)(&As2[kk][ty * 4 + 2]);
            ulonglong2 bb  = *(const ulonglong2*)(&Bs[kk][tx * 4]);
            fma2(acc[0][0], a01.x, bb.x); fma2(acc[0][1], a01.x, bb.y);
            fma2(acc[1][0], a01.y, bb.x); fma2(acc[1][1], a01.y, bb.y);
            fma2(acc[2][0], a23.x, bb.x); fma2(acc[2][1], a23.x, bb.y);
            fma2(acc[3][0], a23.y, bb.x); fma2(acc[3][1], a23.y, bb.y);
        }
        __syncthreads();
    }

    const int col = n0 + tx * 4;
    float4 bb = *(const float4*)(bia + col);
    #pragma unroll
    for (int i = 0; i < 4; i++) {
        int row = m0 + ty * 4 + i;
        float2 c01 = unpack2(acc[i][0]);
        float2 c23 = unpack2(acc[i][1]);
        float4 o;
        o.x = fmaxf(c01.x + bb.x, 0.0f);
        o.y = fmaxf(c01.y + bb.y, 0.0f);
        o.z = fmaxf(c23.x + bb.z, 0.0f);
        o.w = fmaxf(c23.y + bb.w, 0.0f);
        *(float4*)(H + row * H2_ + col) = o;
    }
}

// ---------------------------------------------------------------------------
// GEMM2: out = H @ W2 + b2. mu: store mu. lv: lv=tanh(.), iv=exp(-lv).
// BM=32, BN=64, BK=16, 256 thr, 2x4 micro via FFMA2. grid (2,16,2)=64 blocks.
// ---------------------------------------------------------------------------
__global__ __launch_bounds__(256) void k_gemm2(
    const float* __restrict__ W2mu, const float* __restrict__ b2mu,
    const float* __restrict__ W2lv, const float* __restrict__ b2lv)
{
    const bool  lvp  = (blockIdx.z != 0);
    const float* Hh  = lvp ? g_Hlv : g_Hmu;
    const float* W   = lvp ? W2lv : W2mu;
    const float* bia = lvp ? b2lv : b2mu;

    __shared__ u64   As2[16][32];
    __shared__ float Bs [16][64];

    const int tid = threadIdx.x;
    const int tx  = tid & 15;
    const int ty  = tid >> 4;
    const int m0  = blockIdx.y * 32;
    const int n0  = blockIdx.x * 64;

    const int arow = tid >> 3;          // 0..31
    const int ak   = (tid & 7) << 1;    // 0..14
    const int brow = tid >> 4;          // 0..15
    const int bcol = (tid & 15) << 2;   // 0..60

    u64 acc[2][2] = {};

    for (int k0 = 0; k0 < H2_; k0 += 16) {
        float2 a2 = *(const float2*)(Hh + (m0 + arow) * H2_ + k0 + ak);
        float4 b4 = *(const float4*)(W + (k0 + brow) * YD + n0 + bcol);
        As2[ak + 0][arow] = pack2(a2.x, a2.x);
        As2[ak + 1][arow] = pack2(a2.y, a2.y);
        *(float4*)(&Bs[brow][bcol]) = b4;
        __syncthreads();

        #pragma unroll
        for (int kk = 0; kk < 16; kk++) {
            ulonglong2 aa = *(const ulonglong2*)(&As2[kk][ty * 2]);
            ulonglong2 bb = *(const ulonglong2*)(&Bs[kk][tx * 4]);
            fma2(acc[0][0], aa.x, bb.x); fma2(acc[0][1], aa.x, bb.y);
            fma2(acc[1][0], aa.y, bb.x); fma2(acc[1][1], aa.y, bb.y);
        }
        __syncthreads();
    }

    const int col = n0 + tx * 4;
    float4 bb = *(const float4*)(bia + col);
    #pragma unroll
    for (int i = 0; i < 2; i++) {
        int row = m0 + ty * 2 + i;
        float2 c01 = unpack2(acc[i][0]);
        float2 c23 = unpack2(acc[i][1]);
        float s0 = c01.x + bb.x;
        float s1 = c01.y + bb.y;
        float s2 = c23.x + bb.z;
        float s3 = c23.y + bb.w;
        if (!lvp) {
            float4 o = {s0, s1, s2, s3};
            *(float4*)(g_mu + row * YD + col) = o;
        } else {
            float t0 = tanhf(s0), t1 = tanhf(s1), t2 = tanhf(s2), t3 = tanhf(s3);
            float4 ol = {t0, t1, t2, t3};
            float4 oi = {expf(-t0), expf(-t1), expf(-t2), expf(-t3)};
            *(float4*)(g_lv + row * YD + col) = ol;
            *(float4*)(g_iv + row * YD + col) = oi;
        }
    }
}

// ---------------------------------------------------------------------------
// y column stats, partitioned: block p sums 32 rows into g_SyP[p], g_Sy2P[p].
// Dual accumulators to break the fp64 dependency chain.
// ---------------------------------------------------------------------------
__global__ __launch_bounds__(YD) void k_ystats(const float* __restrict__ Y)
{
    const int d = threadIdx.x;
    const int p = blockIdx.x;
    const int j0 = p * (B_ / NPART);
    double sy0 = 0.0, sy1 = 0.0, sy20 = 0.0, sy21 = 0.0;
    #pragma unroll 4
    for (int j = j0; j < j0 + B_ / NPART; j += 2) {
        double v0 = (double)Y[j * YD + d];
        double v1 = (double)Y[(j + 1) * YD + d];
        sy0 += v0; sy20 = fma(v0, v0, sy20);
        sy1 += v1; sy21 = fma(v1, v1, sy21);
    }
    g_SyP [p][d] = sy0 + sy1;
    g_Sy2P[p][d] = sy20 + sy21;
}

// ---------------------------------------------------------------------------
// Per-row reductions: one warp per row, shuffle reduce (fp64 accumulation).
//  pos_i = sum_d [-0.5 (mu-y)^2 iv - 0.5 lv]
//  all_i = sum_d [-0.5 iv (Sy2 - 2 mu Sy + 512 mu^2) - 256 lv]
// 256 thr = 8 warps/block, grid 64. Sy partials folded once per block.
// ---------------------------------------------------------------------------
__global__ __launch_bounds__(256) void k_rows(const float* __restrict__ Y)
{
    __shared__ double sSy[YD];
    __shared__ double sSy2[YD];
    const int tid  = threadIdx.x;
    if (tid < YD) {
        double s = 0.0, s2 = 0.0;
        #pragma unroll
        for (int p = 0; p < NPART; p++) { s += g_SyP[p][tid]; s2 += g_Sy2P[p][tid]; }
        sSy[tid] = s; sSy2[tid] = s2;
    }
    __syncthreads();

    const int lane = tid & 31;
    const int wid  = tid >> 5;
    const int i    = blockIdx.x * 8 + wid;

    double pos = 0.0, row = 0.0;
    #pragma unroll
    for (int q = 0; q < 4; q++) {
        int d = q * 32 + lane;
        float muf = g_mu[i * YD + d];
        float lvf = g_lv[i * YD + d];
        float ivf = g_iv[i * YD + d];
        float yf  = Y   [i * YD + d];

        float dmy = muf - yf;
        pos += (double)fmaf(-0.5f * dmy * dmy, ivf, -0.5f * lvf);

        double mu = (double)muf;
        double t  = fma(mu, fma(512.0, mu, -2.0 * sSy[d]), sSy2[d]);
        row = fma(-0.5 * (double)ivf, t, row);
        row = fma(-256.0, (double)lvf, row);
    }
    #pragma unroll
    for (int off = 16; off > 0; off >>= 1) {
        pos += __shfl_down_sync(0xffffffffu, pos, off);
        row += __shfl_down_sync(0xffffffffu, row, off);
    }
    if (lane == 0) {
        g_pos_row[i] = pos;
        g_all_row[i] = row;
    }
}

// ---------------------------------------------------------------------------
// Final deterministic tree reduce: out = mean(pos) - mean(all_probs)
// (logsumexp collapses: 511 + e^-20 == 511 in fp32, log(B-1) cancels exactly)
// ---------------------------------------------------------------------------
__global__ __launch_bounds__(B_) void k_final(float* __restrict__ out, int out_size)
{
    const int t = threadIdx.x;
    __shared__ double sp[B_];
    __shared__ double sa[B_];
    sp[t] = g_pos_row[t];
    sa[t] = g_all_row[t];
    __syncthreads();
    #pragma unroll
    for (int s = B_ / 2; s > 0; s >>= 1) {
        if (t < s) { sp[t] += sp[t + s]; sa[t] += sa[t + s]; }
        __syncthreads();
    }
    if (t == 0) {
        double res = sp[0] / 512.0 - sa[0] / (512.0 * 512.0);
        out[0] = (float)res;
    }
    for (int k = t + 1; k < out_size; k += B_) out[k] = 0.0f;
}

// ---------------------------------------------------------------------------
extern "C" void kernel_launch(void* const* d_in, const int* in_sizes, int n_in,
                              void* d_out, int out_size)
{
    const float* x   = (const float*)d_in[0];
    const float* y   = (const float*)d_in[1];
    const float* w1m = (const float*)d_in[2];
    const float* b1m = (const float*)d_in[3];
    const float* w2m = (const float*)d_in[4];
    const float* b2m = (const float*)d_in[5];
    const float* w1l = (const float*)d_in[6];
    const float* b1l = (const float*)d_in[7];
    const float* w2l = (const float*)d_in[8];
    const float* b2l = (const float*)d_in[9];

    dim3 g1(H2_ / 64, B_ / 64, 2);   // (8, 8, 2) = 128 blocks
    k_gemm1<<<g1, 256>>>(x, w1m, b1m, w1l, b1l);

    dim3 g2(YD / 64, B_ / 32, 2);    // (2, 16, 2) = 64 blocks
    k_gemm2<<<g2, 256>>>(w2m, b2m, w2l, b2l);

    k_ystats<<<NPART, YD>>>(y);
    k_rows<<<B_ / 8, 256>>>(y);
    k_final<<<1, B_>>>((float*)d_out, out_size);
}

// round 3
// speedup vs baseline: 1.6613x; 1.2089x over previous
#include <cuda_runtime.h>
#include <math.h>

// Problem dims (fixed by the reference)
#define B_  512
#define XD  768
#define YD  128
#define H2_ 512
#define NPART 16

typedef unsigned long long u64;

// Scratch (no allocations allowed -> __device__ globals)
__device__ float  g_Hmu[B_ * H2_];
__device__ float  g_Hlv[B_ * H2_];
__device__ float  g_mu [B_ * YD];
__device__ float  g_lv [B_ * YD];
__device__ float  g_iv [B_ * YD];
__device__ double g_SyP [NPART][YD];
__device__ double g_Sy2P[NPART][YD];
__device__ double g_pos_row[B_];
__device__ double g_all_row[B_];
__device__ unsigned int g_ctr = 0;

// ---------------- f32x2 packed-FMA helpers (Blackwell FFMA2) ----------------
__device__ __forceinline__ u64 pack2(float lo, float hi) {
    u64 r; asm("mov.b64 %0, {%1, %2};" : "=l"(r) : "f"(lo), "f"(hi)); return r;
}
__device__ __forceinline__ void fma2(u64 &d, u64 a, u64 b) {
    asm("fma.rn.f32x2 %0, %1, %2, %0;" : "+l"(d) : "l"(a), "l"(b));
}
__device__ __forceinline__ float2 unpack2(u64 v) {
    float2 f; asm("mov.b64 {%0, %1}, %2;" : "=f"(f.x), "=f"(f.y) : "l"(v)); return f;
}

// ---------------------------------------------------------------------------
// Kernel A: blocks 0..127 = GEMM1 (H = relu(X@W1+b1), both heads),
//           blocks 128..143 = y column stats (fills idle SMs for free).
// GEMM1: BM=BN=64, BK=16, 256 thr, 4x4 micro via FFMA2, double-buffered LDG.
// ---------------------------------------------------------------------------
__global__ __launch_bounds__(256) void k_gemm1(
    const float* __restrict__ X,
    const float* __restrict__ Y,
    const float* __restrict__ Wmu, const float* __restrict__ bmu,
    const float* __restrict__ Wlv, const float* __restrict__ blv)
{
    const int b = blockIdx.x;

    if (b >= 128) {
        // ---- ystats role: block p sums 32 rows of Y into fp64 partials ----
        const int p = b - 128;
        const int d = threadIdx.x;
        if (d < YD) {
            const int j0 = p * (B_ / NPART);
            double sy0 = 0.0, sy1 = 0.0, sy20 = 0.0, sy21 = 0.0;
            #pragma unroll 4
            for (int j = j0; j < j0 + B_ / NPART; j += 2) {
                double v0 = (double)Y[j * YD + d];
                double v1 = (double)Y[(j + 1) * YD + d];
                sy0 += v0; sy20 = fma(v0, v0, sy20);
                sy1 += v1; sy21 = fma(v1, v1, sy21);
            }
            g_SyP [p][d] = sy0 + sy1;
            g_Sy2P[p][d] = sy20 + sy21;
        }
        return;
    }

    // ---- GEMM1 role ----
    const bool  lvp = (b & 1);
    const int   t   = b >> 1;            // 0..63
    const int   n0  = (t & 7) * 64;
    const int   m0  = (t >> 3) * 64;
    const float* W   = lvp ? Wlv : Wmu;
    const float* bia = lvp ? blv : bmu;
    float*       H   = lvp ? g_Hlv : g_Hmu;

    __shared__ u64   As2[16][64];   // [k][m], duplicated {a,a}
    __shared__ float Bs [16][64];   // [k][n]

    const int tid = threadIdx.x;
    const int tx  = tid & 15;
    const int ty  = tid >> 4;

    const int arow = tid >> 2;           // 0..63
    const int ak   = (tid & 3) << 2;     // 0,4,8,12
    const int brow = tid >> 4;           // 0..15
    const int bcol = (tid & 15) << 2;    // 0..60

    const float* Xp = X + (m0 + arow) * XD + ak;
    const float* Wp = W + brow * H2_ + n0 + bcol;

    u64 acc[4][2] = {};

    float4 a4 = *(const float4*)(Xp);
    float4 b4 = *(const float4*)(Wp);

    const int k_iters = XD / 16;  // 48
    for (int it = 0; it < k_iters; it++) {
        As2[ak + 0][arow] = pack2(a4.x, a4.x);
        As2[ak + 1][arow] = pack2(a4.y, a4.y);
        As2[ak + 2][arow] = pack2(a4.z, a4.z);
        As2[ak + 3][arow] = pack2(a4.w, a4.w);
        *(float4*)(&Bs[brow][bcol]) = b4;
        __syncthreads();

        if (it + 1 < k_iters) {
            a4 = *(const float4*)(Xp + (it + 1) * 16);
            b4 = *(const float4*)(Wp + (it + 1) * 16 * H2_);
        }

        #pragma unroll
        for (int kk = 0; kk < 16; kk++) {
            ulonglong2 a01 = *(const ulonglong2*)(&As2[kk][ty * 4 + 0]);
            ulonglong2 a23 = *(const ulonglong2*)(&As2[kk][ty * 4 + 2]);
            ulonglong2 bb  = *(const ulonglong2*)(&Bs[kk][tx * 4]);
            fma2(acc[0][0], a01.x, bb.x); fma2(acc[0][1], a01.x, bb.y);
            fma2(acc[1][0], a01.y, bb.x); fma2(acc[1][1], a01.y, bb.y);
            fma2(acc[2][0], a23.x, bb.x); fma2(acc[2][1], a23.x, bb.y);
            fma2(acc[3][0], a23.y, bb.x); fma2(acc[3][1], a23.y, bb.y);
        }
        __syncthreads();
    }

    const int col = n0 + tx * 4;
    float4 bb = *(const float4*)(bia + col);
    #pragma unroll
    for (int i = 0; i < 4; i++) {
        int row = m0 + ty * 4 + i;
        float2 c01 = unpack2(acc[i][0]);
        float2 c23 = unpack2(acc[i][1]);
        float4 o;
        o.x = fmaxf(c01.x + bb.x, 0.0f);
        o.y = fmaxf(c01.y + bb.y, 0.0f);
        o.z = fmaxf(c23.x + bb.z, 0.0f);
        o.w = fmaxf(c23.y + bb.w, 0.0f);
        *(float4*)(H + row * H2_ + col) = o;
    }
}

// ---------------------------------------------------------------------------
// GEMM2: out = H @ W2 + b2. mu: store mu. lv: lv=tanh(.), iv=exp(-lv).
// BM=32, BN=64, BK=16, 256 thr, 2x4 micro via FFMA2, double-buffered.
// grid (2,16,2) = 64 blocks.
// ---------------------------------------------------------------------------
__global__ __launch_bounds__(256) void k_gemm2(
    const float* __restrict__ W2mu, const float* __restrict__ b2mu,
    const float* __restrict__ W2lv, const float* __restrict__ b2lv)
{
    const bool  lvp  = (blockIdx.z != 0);
    const float* Hh  = lvp ? g_Hlv : g_Hmu;
    const float* W   = lvp ? W2lv : W2mu;
    const float* bia = lvp ? b2lv : b2mu;

    __shared__ u64   As2[16][32];
    __shared__ float Bs [16][64];

    const int tid = threadIdx.x;
    const int tx  = tid & 15;
    const int ty  = tid >> 4;
    const int m0  = blockIdx.y * 32;
    const int n0  = blockIdx.x * 64;

    const int arow = tid >> 3;          // 0..31
    const int ak   = (tid & 7) << 1;    // 0..14
    const int brow = tid >> 4;          // 0..15
    const int bcol = (tid & 15) << 2;   // 0..60

    const float* Hp = Hh + (m0 + arow) * H2_ + ak;
    const float* Wp = W + brow * YD + n0 + bcol;

    u64 acc[2][2] = {};

    float2 a2 = *(const float2*)(Hp);
    float4 b4 = *(const float4*)(Wp);

    const int k_iters = H2_ / 16;  // 32
    for (int it = 0; it < k_iters; it++) {
        As2[ak + 0][arow] = pack2(a2.x, a2.x);
        As2[ak + 1][arow] = pack2(a2.y, a2.y);
        *(float4*)(&Bs[brow][bcol]) = b4;
        __syncthreads();

        if (it + 1 < k_iters) {
            a2 = *(const float2*)(Hp + (it + 1) * 16);
            b4 = *(const float4*)(Wp + (it + 1) * 16 * YD);
        }

        #pragma unroll
        for (int kk = 0; kk < 16; kk++) {
            ulonglong2 aa = *(const ulonglong2*)(&As2[kk][ty * 2]);
            ulonglong2 bb = *(const ulonglong2*)(&Bs[kk][tx * 4]);
            fma2(acc[0][0], aa.x, bb.x); fma2(acc[0][1], aa.x, bb.y);
            fma2(acc[1][0], aa.y, bb.x); fma2(acc[1][1], aa.y, bb.y);
        }
        __syncthreads();
    }

    const int col = n0 + tx * 4;
    float4 bb = *(const float4*)(bia + col);
    #pragma unroll
    for (int i = 0; i < 2; i++) {
        int row = m0 + ty * 2 + i;
        float2 c01 = unpack2(acc[i][0]);
        float2 c23 = unpack2(acc[i][1]);
        float s0 = c01.x + bb.x;
        float s1 = c01.y + bb.y;
        float s2 = c23.x + bb.z;
        float s3 = c23.y + bb.w;
        if (!lvp) {
            float4 o = {s0, s1, s2, s3};
            *(float4*)(g_mu + row * YD + col) = o;
        } else {
            float t0 = tanhf(s0), t1 = tanhf(s1), t2 = tanhf(s2), t3 = tanhf(s3);
            float4 ol = {t0, t1, t2, t3};
            float4 oi = {expf(-t0), expf(-t1), expf(-t2), expf(-t3)};
            *(float4*)(g_lv + row * YD + col) = ol;
            *(float4*)(g_iv + row * YD + col) = oi;
        }
    }
}

// ---------------------------------------------------------------------------
// Kernel C: per-row reductions + final scalar, fused via last-block ticket.
// grid 128 x 128 thr; one warp per row (4 rows/block).
//  pos_i = sum_d [-0.5 (mu-y)^2 iv - 0.5 lv]
//  all_i = sum_d [-0.5 iv (Sy2 - 2 mu Sy + 512 mu^2) - 256 lv]
// negative == all_probs exactly in fp32 (511 + e^-20 == 511; log(B-1) cancels)
// ---------------------------------------------------------------------------
__global__ __launch_bounds__(128) void k_rows_final(
    const float* __restrict__ Y, float* __restrict__ out, int out_size)
{
    __shared__ double sSy[YD];
    __shared__ double sSy2[YD];
    __shared__ bool s_last;

    const int tid = threadIdx.x;

    // Fold y-stat partials (redundant per block, tiny)
    {
        double s = 0.0, s2 = 0.0;
        #pragma unroll
        for (int p = 0; p < NPART; p++) { s += g_SyP[p][tid]; s2 += g_Sy2P[p][tid]; }
        sSy[tid] = s; sSy2[tid] = s2;
    }
    __syncthreads();

    const int lane = tid & 31;
    const int wid  = tid >> 5;
    const int i    = blockIdx.x * 4 + wid;

    double pos = 0.0, row = 0.0;
    #pragma unroll
    for (int q = 0; q < 4; q++) {
        int d = q * 32 + lane;
        float muf = g_mu[i * YD + d];
        float lvf = g_lv[i * YD + d];
        float ivf = g_iv[i * YD + d];
        float yf  = Y   [i * YD + d];

        float dmy = muf - yf;
        pos += (double)fmaf(-0.5f * dmy * dmy, ivf, -0.5f * lvf);

        double mu = (double)muf;
        double tq = fma(mu, fma(512.0, mu, -2.0 * sSy[d]), sSy2[d]);
        row = fma(-0.5 * (double)ivf, tq, row);
        row = fma(-256.0, (double)lvf, row);
    }
    #pragma unroll
    for (int off = 16; off > 0; off >>= 1) {
        pos += __shfl_down_sync(0xffffffffu, pos, off);
        row += __shfl_down_sync(0xffffffffu, row, off);
    }
    if (lane == 0) {
        g_pos_row[i] = pos;
        g_all_row[i] = row;
        __threadfence();
    }
    __syncthreads();

    if (tid == 0) {
        unsigned old = atomicAdd(&g_ctr, 1u);
        s_last = (old == gridDim.x - 1);
    }
    __syncthreads();
    if (!s_last) return;

    // ---- last block: deterministic final reduce over 512 rows ----
    double p0 = 0.0, a0 = 0.0;
    #pragma unroll
    for (int j = tid; j < B_; j += 128) {
        p0 += g_pos_row[j];
        a0 += g_all_row[j];
    }
    sSy[tid]  = p0;   // reuse shared buffers
    sSy2[tid] = a0;
    __syncthreads();
    #pragma unroll
    for (int s = 64; s > 0; s >>= 1) {
        if (tid < s) { sSy[tid] += sSy[tid + s]; sSy2[tid] += sSy2[tid + s]; }
        __syncthreads();
    }
    if (tid == 0) {
        double res = sSy[0] / 512.0 - sSy2[0] / (512.0 * 512.0);
        out[0] = (float)res;
        g_ctr = 0;  // reset for next graph replay
    }
    for (int k = tid + 1; k < out_size; k += 128) out[k] = 0.0f;
}

// ---------------------------------------------------------------------------
extern "C" void kernel_launch(void* const* d_in, const int* in_sizes, int n_in,
                              void* d_out, int out_size)
{
    const float* x   = (const float*)d_in[0];
    const float* y   = (const float*)d_in[1];
    const float* w1m = (const float*)d_in[2];
    const float* b1m = (const float*)d_in[3];
    const float* w2m = (const float*)d_in[4];
    const float* b2m = (const float*)d_in[5];
    const float* w1l = (const float*)d_in[6];
    const float* b1l = (const float*)d_in[7];
    const float* w2l = (const float*)d_in[8];
    const float* b2l = (const float*)d_in[9];

    k_gemm1<<<128 + NPART, 256>>>(x, y, w1m, b1m, w1l, b1l);

    dim3 g2(YD / 64, B_ / 32, 2);    // (2, 16, 2) = 64 blocks
    k_gemm2<<<g2, 256>>>(w2m, b2m, w2l, b2l);

    k_rows_final<<<B_ / 4, 128>>>(y, (float*)d_out, out_size);
}

// round 4
// speedup vs baseline: 2.1619x; 1.3013x over previous
#include <cuda_runtime.h>
#include <math.h>

// Problem dims (fixed by the reference)
#define B_  512
#define XD  768
#define YD  128
#define H2_ 512
#define NPART 16

typedef unsigned long long u64;

// Scratch (no allocations allowed -> __device__ globals)
// gemm1 raw partials: [head][ksplit] over (B_, H2_)
__device__ float  g_H[2][2][B_ * H2_];
// gemm2 raw partials: [head][ksplit] over (B_, YD)
__device__ float  g_Q[2][2][B_ * YD];
__device__ double g_SyP [NPART][YD];
__device__ double g_Sy2P[NPART][YD];
__device__ double g_pos_row[B_];
__device__ double g_all_row[B_];
__device__ unsigned int g_ctr = 0;

// ---------------- f32x2 packed-FMA helpers (Blackwell FFMA2) ----------------
__device__ __forceinline__ u64 pack2(float lo, float hi) {
    u64 r; asm("mov.b64 %0, {%1, %2};" : "=l"(r) : "f"(lo), "f"(hi)); return r;
}
__device__ __forceinline__ void fma2(u64 &d, u64 a, u64 b) {
    asm("fma.rn.f32x2 %0, %1, %2, %0;" : "+l"(d) : "l"(a), "l"(b));
}
__device__ __forceinline__ float2 unpack2(u64 v) {
    float2 f; asm("mov.b64 {%0, %1}, %2;" : "=f"(f.x), "=f"(f.y) : "l"(v)); return f;
}

// ---------------------------------------------------------------------------
// Kernel A: blocks 0..255 = GEMM1 K-split partials (X@W1, no bias/relu yet),
//           blocks 256..271 = y column stats.
// Block b: head=b&1, ksplit=(b>>1)&1, tile t=b>>2 -> 64x64 tile, K range 384.
// BM=BN=64, BK=16, 256 thr, 4x4 micro via FFMA2. ~2 blocks/SM.
// ---------------------------------------------------------------------------
__global__ __launch_bounds__(256) void k_gemm1(
    const float* __restrict__ X,
    const float* __restrict__ Y,
    const float* __restrict__ Wmu,
    const float* __restrict__ Wlv)
{
    const int b = blockIdx.x;

    if (b >= 256) {
        // ---- ystats role ----
        const int p = b - 256;
        const int d = threadIdx.x;
        if (d < YD) {
            const int j0 = p * (B_ / NPART);
            double sy0 = 0.0, sy1 = 0.0, sy20 = 0.0, sy21 = 0.0;
            #pragma unroll 4
            for (int j = j0; j < j0 + B_ / NPART; j += 2) {
                double v0 = (double)Y[j * YD + d];
                double v1 = (double)Y[(j + 1) * YD + d];
                sy0 += v0; sy20 = fma(v0, v0, sy20);
                sy1 += v1; sy21 = fma(v1, v1, sy21);
            }
            g_SyP [p][d] = sy0 + sy1;
            g_Sy2P[p][d] = sy20 + sy21;
        }
        return;
    }

    // ---- GEMM1 partial role ----
    const int head = b & 1;
    const int ks   = (b >> 1) & 1;
    const int t    = b >> 2;             // 0..63
    const int n0   = (t & 7) * 64;
    const int m0   = (t >> 3) * 64;
    const float* W = head ? Wlv : Wmu;
    float*       P = g_H[head][ks];

    __shared__ u64   As2[16][64];   // [k][m], duplicated {a,a}
    __shared__ float Bs [16][64];   // [k][n]

    const int tid = threadIdx.x;
    const int tx  = tid & 15;
    const int ty  = tid >> 4;

    const int arow = tid >> 2;           // 0..63
    const int ak   = (tid & 3) << 2;     // 0,4,8,12
    const int brow = tid >> 4;           // 0..15
    const int bcol = (tid & 15) << 2;    // 0..60

    const int kbase = ks * (XD / 2);     // 0 or 384
    const float* Xp = X + (m0 + arow) * XD + kbase + ak;
    const float* Wp = W + (kbase + brow) * H2_ + n0 + bcol;

    u64 acc[4][2] = {};

    float4 a4 = *(const float4*)(Xp);
    float4 b4 = *(const float4*)(Wp);

    const int k_iters = XD / 2 / 16;  // 24
    for (int it = 0; it < k_iters; it++) {
        As2[ak + 0][arow] = pack2(a4.x, a4.x);
        As2[ak + 1][arow] = pack2(a4.y, a4.y);
        As2[ak + 2][arow] = pack2(a4.z, a4.z);
        As2[ak + 3][arow] = pack2(a4.w, a4.w);
        *(float4*)(&Bs[brow][bcol]) = b4;
        __syncthreads();

        if (it + 1 < k_iters) {
            a4 = *(const float4*)(Xp + (it + 1) * 16);
            b4 = *(const float4*)(Wp + (it + 1) * 16 * H2_);
        }

        #pragma unroll
        for (int kk = 0; kk < 16; kk++) {
            ulonglong2 a01 = *(const ulonglong2*)(&As2[kk][ty * 4 + 0]);
            ulonglong2 a23 = *(const ulonglong2*)(&As2[kk][ty * 4 + 2]);
            ulonglong2 bb  = *(const ulonglong2*)(&Bs[kk][tx * 4]);
            fma2(acc[0][0], a01.x, bb.x); fma2(acc[0][1], a01.x, bb.y);
            fma2(acc[1][0], a01.y, bb.x); fma2(acc[1][1], a01.y, bb.y);
            fma2(acc[2][0], a23.x, bb.x); fma2(acc[2][1], a23.x, bb.y);
            fma2(acc[3][0], a23.y, bb.x); fma2(acc[3][1], a23.y, bb.y);
        }
        __syncthreads();
    }

    const int col = n0 + tx * 4;
    #pragma unroll
    for (int i = 0; i < 4; i++) {
        int row = m0 + ty * 4 + i;
        float2 c01 = unpack2(acc[i][0]);
        float2 c23 = unpack2(acc[i][1]);
        float4 o = {c01.x, c01.y, c23.x, c23.y};
        *(float4*)(P + row * H2_ + col) = o;
    }
}

// ---------------------------------------------------------------------------
// GEMM2 partials: Q[head][ks] = relu(H0+H1+b1) @ W2-slice (raw, no epilogue).
// A-loader fuses the gemm1 partial-sum + bias + relu.
// BM=32, BN=64, BK=16, 256 thr, 2x4 micro via FFMA2.
// grid (2, 16, 4): z = head*2 + ksplit. 128 blocks.
// ---------------------------------------------------------------------------
__global__ __launch_bounds__(256) void k_gemm2(
    const float* __restrict__ b1mu, const float* __restrict__ b1lv,
    const float* __restrict__ W2mu, const float* __restrict__ W2lv)
{
    const int  head = blockIdx.z >> 1;
    const int  ks   = blockIdx.z & 1;
    const float* H0 = g_H[head][0];
    const float* H1 = g_H[head][1];
    const float* b1 = head ? b1lv : b1mu;
    const float* W  = head ? W2lv : W2mu;
    float*       Q  = g_Q[head][ks];

    __shared__ u64   As2[16][32];
    __shared__ float Bs [16][64];

    const int tid = threadIdx.x;
    const int tx  = tid & 15;
    const int ty  = tid >> 4;
    const int m0  = blockIdx.y * 32;
    const int n0  = blockIdx.x * 64;

    const int arow = tid >> 3;          // 0..31
    const int ak   = (tid & 7) << 1;    // 0..14
    const int brow = tid >> 4;          // 0..15
    const int bcol = (tid & 15) << 2;   // 0..60

    const int kbase = ks * (H2_ / 2);   // 0 or 256
    const float* H0p = H0 + (m0 + arow) * H2_ + kbase + ak;
    const float* H1p = H1 + (m0 + arow) * H2_ + kbase + ak;
    const float* b1p = b1 + kbase + ak;
    const float* Wp  = W + (kbase + brow) * YD + n0 + bcol;

    u64 acc[2][2] = {};

    float2 p0 = *(const float2*)(H0p);
    float2 p1 = *(const float2*)(H1p);
    float2 bv = *(const float2*)(b1p);
    float4 b4 = *(const float4*)(Wp);

    const int k_iters = H2_ / 2 / 16;  // 16
    for (int it = 0; it < k_iters; it++) {
        float ax = fmaxf(p0.x + p1.x + bv.x, 0.0f);
        float ay = fmaxf(p0.y + p1.y + bv.y, 0.0f);
        As2[ak + 0][arow] = pack2(ax, ax);
        As2[ak + 1][arow] = pack2(ay, ay);
        *(float4*)(&Bs[brow][bcol]) = b4;
        __syncthreads();

        if (it + 1 < k_iters) {
            p0 = *(const float2*)(H0p + (it + 1) * 16);
            p1 = *(const float2*)(H1p + (it + 1) * 16);
            bv = *(const float2*)(b1p + (it + 1) * 16);
            b4 = *(const float4*)(Wp + (it + 1) * 16 * YD);
        }

        #pragma unroll
        for (int kk = 0; kk < 16; kk++) {
            ulonglong2 aa = *(const ulonglong2*)(&As2[kk][ty * 2]);
            ulonglong2 bb = *(const ulonglong2*)(&Bs[kk][tx * 4]);
            fma2(acc[0][0], aa.x, bb.x); fma2(acc[0][1], aa.x, bb.y);
            fma2(acc[1][0], aa.y, bb.x); fma2(acc[1][1], aa.y, bb.y);
        }
        __syncthreads();
    }

    const int col = n0 + tx * 4;
    #pragma unroll
    for (int i = 0; i < 2; i++) {
        int row = m0 + ty * 2 + i;
        float2 c01 = unpack2(acc[i][0]);
        float2 c23 = unpack2(acc[i][1]);
        float4 o = {c01.x, c01.y, c23.x, c23.y};
        *(float4*)(Q + row * YD + col) = o;
    }
}

// ---------------------------------------------------------------------------
// Kernel C: epilogue (bias+tanh+exp) + per-row reductions + final scalar.
// grid 128 x 128 thr; one warp per row (4 rows/block), last-block ticket.
//  mu = Qmu0+Qmu1+b2mu;  lv = tanh(Qlv0+Qlv1+b2lv);  iv = exp(-lv)
//  pos_i = sum_d [-0.5 (mu-y)^2 iv - 0.5 lv]
//  all_i = sum_d [-0.5 iv (Sy2 - 2 mu Sy + 512 mu^2) - 256 lv]
// negative == all_probs exactly in fp32 (511 + e^-20 == 511; log(B-1) cancels)
// ---------------------------------------------------------------------------
__global__ __launch_bounds__(128) void k_rows_final(
    const float* __restrict__ Y,
    const float* __restrict__ b2mu, const float* __restrict__ b2lv,
    float* __restrict__ out, int out_size)
{
    __shared__ double sSy[YD];
    __shared__ double sSy2[YD];
    __shared__ bool s_last;

    const int tid = threadIdx.x;

    {
        double s = 0.0, s2 = 0.0;
        #pragma unroll
        for (int p = 0; p < NPART; p++) { s += g_SyP[p][tid]; s2 += g_Sy2P[p][tid]; }
        sSy[tid] = s; sSy2[tid] = s2;
    }
    __syncthreads();

    const int lane = tid & 31;
    const int wid  = tid >> 5;
    const int i    = blockIdx.x * 4 + wid;

    double pos = 0.0, row = 0.0;
    #pragma unroll
    for (int q = 0; q < 4; q++) {
        int d = q * 32 + lane;
        int idx = i * YD + d;
        float muf = g_Q[0][0][idx] + g_Q[0][1][idx] + b2mu[d];
        float sf  = g_Q[1][0][idx] + g_Q[1][1][idx] + b2lv[d];
        float lvf = tanhf(sf);
        float ivf = expf(-lvf);
        float yf  = Y[idx];

        float dmy = muf - yf;
        pos += (double)fmaf(-0.5f * dmy * dmy, ivf, -0.5f * lvf);

        double mu = (double)muf;
        double tq = fma(mu, fma(512.0, mu, -2.0 * sSy[d]), sSy2[d]);
        row = fma(-0.5 * (double)ivf, tq, row);
        row = fma(-256.0, (double)lvf, row);
    }
    #pragma unroll
    for (int off = 16; off > 0; off >>= 1) {
        pos += __shfl_down_sync(0xffffffffu, pos, off);
        row += __shfl_down_sync(0xffffffffu, row, off);
    }
    if (lane == 0) {
        g_pos_row[i] = pos;
        g_all_row[i] = row;
        __threadfence();
    }
    __syncthreads();

    if (tid == 0) {
        unsigned old = atomicAdd(&g_ctr, 1u);
        s_last = (old == gridDim.x - 1);
    }
    __syncthreads();
    if (!s_last) return;

    // ---- last block: deterministic final reduce over 512 rows ----
    double p0 = 0.0, a0 = 0.0;
    #pragma unroll
    for (int j = tid; j < B_; j += 128) {
        p0 += g_pos_row[j];
        a0 += g_all_row[j];
    }
    sSy[tid]  = p0;
    sSy2[tid] = a0;
    __syncthreads();
    #pragma unroll
    for (int s = 64; s > 0; s >>= 1) {
        if (tid < s) { sSy[tid] += sSy[tid + s]; sSy2[tid] += sSy2[tid + s]; }
        __syncthreads();
    }
    if (tid == 0) {
        double res = sSy[0] / 512.0 - sSy2[0] / (512.0 * 512.0);
        out[0] = (float)res;
        g_ctr = 0;  // reset for next graph replay
    }
    for (int k = tid + 1; k < out_size; k += 128) out[k] = 0.0f;
}

// ---------------------------------------------------------------------------
extern "C" void kernel_launch(void* const* d_in, const int* in_sizes, int n_in,
                              void* d_out, int out_size)
{
    const float* x   = (const float*)d_in[0];
    const float* y   = (const float*)d_in[1];
    const float* w1m = (const float*)d_in[2];
    const float* b1m = (const float*)d_in[3];
    const float* w2m = (const float*)d_in[4];
    const float* b2m = (const float*)d_in[5];
    const float* w1l = (const float*)d_in[6];
    const float* b1l = (const float*)d_in[7];
    const float* w2l = (const float*)d_in[8];
    const float* b2l = (const float*)d_in[9];

    k_gemm1<<<256 + NPART, 256>>>(x, y, w1m, w1l);

    dim3 g2(YD / 64, B_ / 32, 4);    // (2, 16, 4) = 128 blocks
    k_gemm2<<<g2, 256>>>(b1m, b1l, w2m, w2l);

    k_rows_final<<<B_ / 4, 128>>>(y, b2m, b2l, (float*)d_out, out_size);
}